// round 14
// baseline (speedup 1.0000x reference)
#include <cuda_runtime.h>

// Problem constants (fixed shapes from reference setup_inputs)
#define BB   8
#define CC   128
#define HH   128
#define WW   128
#define HO   256            // HH * 2
#define WO   256            // WW * 2
#define HW   (HH * WW)      // 16384
#define HOWO (HO * WO)      // 65536

__global__ __launch_bounds__(256)
void LaU_upsample_kernel(const float* __restrict__ in,
                         const float* __restrict__ offx,
                         const float* __restrict__ offy,
                         float* __restrict__ out)
{
    const int idx = blockIdx.x * 256 + threadIdx.x;   // 0 .. B*HO*WO-1
    const int wo = idx & (WO - 1);
    const int ho = (idx >> 8) & (HO - 1);
    const int b  = idx >> 16;

    const int so = b * HOWO + ho * WO + wo;           // spatial index (offsets)

    // sample coordinates (shared by all 128 channels)
    const float x = 0.5f * (float)wo + offx[so];
    const float y = 0.5f * (float)ho + offy[so];

    const float x0f = floorf(x);
    const float y0f = floorf(y);
    const float wx = x - x0f;
    const float wy = y - y0f;
    const int x0 = (int)x0f;
    const int y0 = (int)y0f;
    const int x1 = x0 + 1;
    const int y1 = y0 + 1;

    const bool vx0 = (x0 >= 0) && (x0 < WW);
    const bool vx1 = (x1 >= 0) && (x1 < WW);
    const bool vy0 = (y0 >= 0) && (y0 < HH);
    const bool vy1 = (y1 >= 0) && (y1 < HH);

    // fold validity into weights: invalid tap contributes exactly 0
    const float w00 = (vy0 && vx0) ? (1.0f - wy) * (1.0f - wx) : 0.0f;
    const float w01 = (vy0 && vx1) ? (1.0f - wy) * wx          : 0.0f;
    const float w10 = (vy1 && vx0) ? wy * (1.0f - wx)          : 0.0f;
    const float w11 = (vy1 && vx1) ? wy * wx                   : 0.0f;

    // clamped (always in-bounds) tap offsets within one channel plane
    const int xc0 = min(max(x0, 0), WW - 1);
    const int xc1 = min(max(x1, 0), WW - 1);
    const int yc0 = min(max(y0, 0), HH - 1);
    const int yc1 = min(max(y1, 0), HH - 1);

    const int o00 = yc0 * WW + xc0;
    const int o01 = yc0 * WW + xc1;
    const int o10 = yc1 * WW + xc0;
    const int o11 = yc1 * WW + xc1;

    const float* __restrict__ pb = in + (size_t)b * CC * HW;
    float* __restrict__ po = out + (size_t)b * CC * HOWO + (size_t)ho * WO + wo;

    #pragma unroll 8
    for (int c = 0; c < CC; ++c) {
        const float* pc = pb + c * HW;
        float v00 = __ldg(pc + o00);
        float v01 = __ldg(pc + o01);
        float v10 = __ldg(pc + o10);
        float v11 = __ldg(pc + o11);
        float v = w00 * v00;
        v = fmaf(w01, v01, v);
        v = fmaf(w10, v10, v);
        v = fmaf(w11, v11, v);
        po[(size_t)c * HOWO] = v;
    }
}

extern "C" void kernel_launch(void* const* d_in, const int* in_sizes, int n_in,
                              void* d_out, int out_size)
{
    const float* in   = (const float*)d_in[0];  // input   (8,128,128,128)
    const float* offx = (const float*)d_in[1];  // offset_x(8,1,256,256)
    const float* offy = (const float*)d_in[2];  // offset_y(8,1,256,256)
    float* out = (float*)d_out;                 // (8,128,256,256)

    const int total = BB * HO * WO;             // 524288 threads
    LaU_upsample_kernel<<<total / 256, 256>>>(in, offx, offy, out);
}

// round 15
// speedup vs baseline: 1.0062x; 1.0062x over previous
#include <cuda_runtime.h>

// Problem constants (fixed shapes from reference setup_inputs)
#define BB   8
#define CC   128
#define HH   128
#define WW   128
#define HO   256            // HH * 2
#define WO   256            // WW * 2
#define HW   (HH * WW)      // 16384
#define HOWO (HO * WO)      // 65536

__global__ __launch_bounds__(256)
void LaU_upsample_kernel(const float* __restrict__ in,
                         const float* __restrict__ offx,
                         const float* __restrict__ offy,
                         float* __restrict__ out)
{
    const int idx = blockIdx.x * 256 + threadIdx.x;   // 0 .. B*HO*WO-1
    const int wo = idx & (WO - 1);
    const int ho = (idx >> 8) & (HO - 1);
    const int b  = idx >> 16;

    const int so = b * HOWO + ho * WO + wo;           // spatial index (offsets)

    // sample coordinates (shared by all 128 channels)
    const float x = 0.5f * (float)wo + offx[so];
    const float y = 0.5f * (float)ho + offy[so];

    const float x0f = floorf(x);
    const float y0f = floorf(y);
    const float wx = x - x0f;
    const float wy = y - y0f;
    const int x0 = (int)x0f;
    const int y0 = (int)y0f;
    const int x1 = x0 + 1;
    const int y1 = y0 + 1;

    const bool vx0 = (x0 >= 0) && (x0 < WW);
    const bool vx1 = (x1 >= 0) && (x1 < WW);
    const bool vy0 = (y0 >= 0) && (y0 < HH);
    const bool vy1 = (y1 >= 0) && (y1 < HH);

    // fold validity into weights: invalid tap contributes exactly 0
    const float w00 = (vy0 && vx0) ? (1.0f - wy) * (1.0f - wx) : 0.0f;
    const float w01 = (vy0 && vx1) ? (1.0f - wy) * wx          : 0.0f;
    const float w10 = (vy1 && vx0) ? wy * (1.0f - wx)          : 0.0f;
    const float w11 = (vy1 && vx1) ? wy * wx                   : 0.0f;

    // clamped (always in-bounds) tap offsets within one channel plane
    const int xc0 = min(max(x0, 0), WW - 1);
    const int xc1 = min(max(x1, 0), WW - 1);
    const int yc0 = min(max(y0, 0), HH - 1);
    const int yc1 = min(max(y1, 0), HH - 1);

    const int o00 = yc0 * WW + xc0;
    const int o01 = yc0 * WW + xc1;
    const int o10 = yc1 * WW + xc0;
    const int o11 = yc1 * WW + xc1;

    const float* __restrict__ pb = in + (size_t)b * CC * HW;
    float* __restrict__ po = out + (size_t)b * CC * HOWO + (size_t)ho * WO + wo;

    #pragma unroll 8
    for (int c = 0; c < CC; ++c) {
        const float* pc = pb + c * HW;
        float v00 = __ldg(pc + o00);
        float v01 = __ldg(pc + o01);
        float v10 = __ldg(pc + o10);
        float v11 = __ldg(pc + o11);
        float v = w00 * v00;
        v = fmaf(w01, v01, v);
        v = fmaf(w10, v10, v);
        v = fmaf(w11, v11, v);
        po[(size_t)c * HOWO] = v;
    }
}

extern "C" void kernel_launch(void* const* d_in, const int* in_sizes, int n_in,
                              void* d_out, int out_size)
{
    const float* in   = (const float*)d_in[0];  // input   (8,128,128,128)
    const float* offx = (const float*)d_in[1];  // offset_x(8,1,256,256)
    const float* offy = (const float*)d_in[2];  // offset_y(8,1,256,256)
    float* out = (float*)d_out;                 // (8,128,256,256)

    const int total = BB * HO * WO;             // 524288 threads
    LaU_upsample_kernel<<<total / 256, 256>>>(in, offx, offy, out);
}